// round 15
// baseline (speedup 1.0000x reference)
#include <cuda_runtime.h>
#include <math.h>

// LatentRNN: B=2048, T=512, P=8, L=64, H=180
// 128 persistent CTAs x 16 batch rows, 640 threads.
// R13 phase C (n=2 pair-packed, PF ring) + retiled B/D (n=2 x 4 rows),
// A-phase fused into E epilogue, 5 barriers/step.

#define B_    2048
#define T_    512
#define P_    8
#define L_    64
#define H_    180
#define IN_K  72
#define BT    16
#define NTHR  640
#define GST   20          // padded row stride for giT/ghT

// packed weights
__device__ float4 g_Wc4 [90 * 540];   // [k2][colpair] fused [W_ih|W_hh] (R13)
__device__ float4 g_Wb4p[36 * 90];    // [k2][colpair] W_in   (K=72)
__device__ float4 g_Wd4a[90 * 90];    // [k2][colpair] W_o1 K 0..179 (h part)
__device__ float4 g_Wd4b[32 * 90];    // [k2][colpair] W_o1 K 180..243 (cur part)
__device__ float4 g_We4 [45 * 64];    // [kq][col] W_o2, K=180 (R13)
__device__ float4 g_Wh4 [16 * 180];   // [kq][col] W_hp, K=64  (R13)

#define N_C  (90 * 540)
#define N_B2 (36 * 90)
#define N_DA (90 * 90)
#define N_DB (32 * 90)
#define N_E  (45 * 64)
#define N_H  (16 * 180)

__global__ void prep_kernel(const float* __restrict__ Wih,
                            const float* __restrict__ Whh,
                            const float* __restrict__ Win,
                            const float* __restrict__ Wo1,
                            const float* __restrict__ Wo2,
                            const float* __restrict__ Whp)
{
    int i = blockIdx.x * blockDim.x + threadIdx.x;
    if (i < N_C) {
        int k2 = i / 540, p = i - k2 * 540;
        int j0 = 2 * p, j1 = j0 + 1;
        int k0 = 2 * k2, k1 = k0 + 1;
        float x = (j0 < 540) ? Wih[j0 * H_ + k0] : Whh[(j0 - 540) * H_ + k0];
        float y = (j1 < 540) ? Wih[j1 * H_ + k0] : Whh[(j1 - 540) * H_ + k0];
        float z = (j0 < 540) ? Wih[j0 * H_ + k1] : Whh[(j0 - 540) * H_ + k1];
        float w = (j1 < 540) ? Wih[j1 * H_ + k1] : Whh[(j1 - 540) * H_ + k1];
        g_Wc4[k2 * 540 + p] = make_float4(x, y, z, w);
        return;
    }
    i -= N_C;
    if (i < N_B2) {
        int k2 = i / 90, p = i - k2 * 90;
        int j0 = 2 * p, k0 = 2 * k2;
        g_Wb4p[k2 * 90 + p] = make_float4(
            Win[j0 * IN_K + k0],       Win[(j0 + 1) * IN_K + k0],
            Win[j0 * IN_K + k0 + 1],   Win[(j0 + 1) * IN_K + k0 + 1]);
        return;
    }
    i -= N_B2;
    if (i < N_DA) {
        int k2 = i / 90, p = i - k2 * 90;
        int j0 = 2 * p, k0 = 2 * k2;
        g_Wd4a[k2 * 90 + p] = make_float4(
            Wo1[j0 * 244 + k0],        Wo1[(j0 + 1) * 244 + k0],
            Wo1[j0 * 244 + k0 + 1],    Wo1[(j0 + 1) * 244 + k0 + 1]);
        return;
    }
    i -= N_DA;
    if (i < N_DB) {
        int k2 = i / 90, p = i - k2 * 90;
        int j0 = 2 * p, k0 = 180 + 2 * k2;
        g_Wd4b[k2 * 90 + p] = make_float4(
            Wo1[j0 * 244 + k0],        Wo1[(j0 + 1) * 244 + k0],
            Wo1[j0 * 244 + k0 + 1],    Wo1[(j0 + 1) * 244 + k0 + 1]);
        return;
    }
    i -= N_DB;
    if (i < N_E) {
        int kq = i / 64, j = i - kq * 64;
        g_We4[kq * 64 + j] = *(const float4*)(Wo2 + j * H_ + kq * 4);
        return;
    }
    i -= N_E;
    if (i < N_H) {
        int kq = i / 180, j = i - kq * 180;
        g_Wh4[kq * 180 + j] = *(const float4*)(Whp + j * L_ + kq * 4);
    }
}

struct __align__(16) Smem {
    float inT [IN_K][BT];      // [phys_t ; cur] transposed (maintained by E)
    float xT  [H_][BT];        // gelu(in @ W_in^T)
    float hT  [2][H_][BT];     // hidden state, double buffered
    float oT  [H_][BT];        // gelu(cat @ W_o1^T)
    float giT [540][GST];      // gi (+bias)
    float ghT [540][GST];      // gh (+bias)
    float catC[L_][BT];        // cur transposed (maintained by E)
    float cur [BT][L_];        // current latents, row-major
    float sb  [1684];          // ih 0 | hh 540 | in 1080 | o1 1260 | o2 1440 | hp 1504
};

__device__ __forceinline__ float gelu_f(float v) {
    return 0.5f * v * (1.0f + erff(v * 0.70710678118654752440f));
}
__device__ __forceinline__ float sigmoid_f(float v) {
    return 1.0f / (1.0f + expf(-v));
}

// n=1 column GEMM (h0 / E): NR rows, K = 4*NKQ, weight float4 at w[kq*STRIDE].
template<int NR, int NKQ, int STRIDE, int LDA>
__device__ __forceinline__ void pcol(const float4* __restrict__ w,
                                     const float* __restrict__ act,
                                     float* __restrict__ acc)
{
#pragma unroll 3
    for (int kq = 0; kq < NKQ; kq++) {
        float4 w4 = w[kq * STRIDE];
        const float* b = act + kq * 4 * LDA;
        float wk[4] = {w4.x, w4.y, w4.z, w4.w};
#pragma unroll
        for (int kk = 0; kk < 4; kk++) {
#pragma unroll
            for (int rq = 0; rq < NR / 4; rq++) {
                float4 a = *(const float4*)(b + kk * LDA + rq * 4);
                acc[rq*4+0] = fmaf(a.x, wk[kk], acc[rq*4+0]);
                acc[rq*4+1] = fmaf(a.y, wk[kk], acc[rq*4+1]);
                acc[rq*4+2] = fmaf(a.z, wk[kk], acc[rq*4+2]);
                acc[rq*4+3] = fmaf(a.w, wk[kk], acc[rq*4+3]);
            }
        }
    }
}

// pair-packed 2-col x 4-row segment: acc0/acc1 over NK2 k-pairs.
template<int NK2, int LDW>
__device__ __forceinline__ void ppair4(const float4* __restrict__ w,
                                       const float* __restrict__ act, int ro,
                                       float* __restrict__ acc0,
                                       float* __restrict__ acc1)
{
#pragma unroll 4
    for (int k2 = 0; k2 < NK2; k2++) {
        float4 w4 = w[k2 * LDW];
        float4 a0 = *(const float4*)(act + (2 * k2) * BT + ro);
        float4 a1 = *(const float4*)(act + (2 * k2 + 1) * BT + ro);
        acc0[0] = fmaf(a0.x, w4.x, acc0[0]); acc1[0] = fmaf(a0.x, w4.y, acc1[0]);
        acc0[1] = fmaf(a0.y, w4.x, acc0[1]); acc1[1] = fmaf(a0.y, w4.y, acc1[1]);
        acc0[2] = fmaf(a0.z, w4.x, acc0[2]); acc1[2] = fmaf(a0.z, w4.y, acc1[2]);
        acc0[3] = fmaf(a0.w, w4.x, acc0[3]); acc1[3] = fmaf(a0.w, w4.y, acc1[3]);
        acc0[0] = fmaf(a1.x, w4.z, acc0[0]); acc1[0] = fmaf(a1.x, w4.w, acc1[0]);
        acc0[1] = fmaf(a1.y, w4.z, acc0[1]); acc1[1] = fmaf(a1.y, w4.w, acc1[1]);
        acc0[2] = fmaf(a1.z, w4.z, acc0[2]); acc1[2] = fmaf(a1.z, w4.w, acc1[2]);
        acc0[3] = fmaf(a1.w, w4.z, acc0[3]); acc1[3] = fmaf(a1.w, w4.w, acc1[3]);
    }
}

// 16 rows x 2 cols FMA for one k (phase C core, from R13).
__device__ __forceinline__ void fma2x16(float* __restrict__ acc0,
                                        float* __restrict__ acc1,
                                        const float* __restrict__ ap,
                                        float wx, float wy)
{
    float4 a0 = *(const float4*)(ap);
    float4 a1 = *(const float4*)(ap + 4);
    float4 a2 = *(const float4*)(ap + 8);
    float4 a3 = *(const float4*)(ap + 12);
    acc0[0]  = fmaf(a0.x, wx, acc0[0]);  acc1[0]  = fmaf(a0.x, wy, acc1[0]);
    acc0[1]  = fmaf(a0.y, wx, acc0[1]);  acc1[1]  = fmaf(a0.y, wy, acc1[1]);
    acc0[2]  = fmaf(a0.z, wx, acc0[2]);  acc1[2]  = fmaf(a0.z, wy, acc1[2]);
    acc0[3]  = fmaf(a0.w, wx, acc0[3]);  acc1[3]  = fmaf(a0.w, wy, acc1[3]);
    acc0[4]  = fmaf(a1.x, wx, acc0[4]);  acc1[4]  = fmaf(a1.x, wy, acc1[4]);
    acc0[5]  = fmaf(a1.y, wx, acc0[5]);  acc1[5]  = fmaf(a1.y, wy, acc1[5]);
    acc0[6]  = fmaf(a1.z, wx, acc0[6]);  acc1[6]  = fmaf(a1.z, wy, acc1[6]);
    acc0[7]  = fmaf(a1.w, wx, acc0[7]);  acc1[7]  = fmaf(a1.w, wy, acc1[7]);
    acc0[8]  = fmaf(a2.x, wx, acc0[8]);  acc1[8]  = fmaf(a2.x, wy, acc1[8]);
    acc0[9]  = fmaf(a2.y, wx, acc0[9]);  acc1[9]  = fmaf(a2.y, wy, acc1[9]);
    acc0[10] = fmaf(a2.z, wx, acc0[10]); acc1[10] = fmaf(a2.z, wy, acc1[10]);
    acc0[11] = fmaf(a2.w, wx, acc0[11]); acc1[11] = fmaf(a2.w, wy, acc1[11]);
    acc0[12] = fmaf(a3.x, wx, acc0[12]); acc1[12] = fmaf(a3.x, wy, acc1[12]);
    acc0[13] = fmaf(a3.y, wx, acc0[13]); acc1[13] = fmaf(a3.y, wy, acc1[13]);
    acc0[14] = fmaf(a3.z, wx, acc0[14]); acc1[14] = fmaf(a3.z, wy, acc1[14]);
    acc0[15] = fmaf(a3.w, wx, acc0[15]); acc1[15] = fmaf(a3.w, wy, acc1[15]);
}

__global__ __launch_bounds__(NTHR, 1)
void latent_rnn_kernel(const float* __restrict__ phys,
                       const float* __restrict__ latents,
                       const float* __restrict__ b_in,
                       const float* __restrict__ b_hp,
                       const float* __restrict__ b_ih,
                       const float* __restrict__ b_hh,
                       const float* __restrict__ b_o1,
                       const float* __restrict__ b_o2,
                       float* __restrict__ out)
{
    extern __shared__ char smem_raw[];
    Smem* s = reinterpret_cast<Smem*>(smem_raw);
    const int tid = threadIdx.x;
    const int b0  = blockIdx.x * BT;

    // ---- init: cur/catC = latents; inT = [phys(0); latents]; biases ----
    for (int i = tid; i < BT * L_; i += NTHR) {
        int r = i >> 6, l = i & 63;
        float v = latents[(b0 + r) * L_ + l];
        s->cur[r][l]       = v;
        s->catC[l][r]      = v;
        s->inT[P_ + l][r]  = v;
    }
    for (int i = tid; i < BT * P_; i += NTHR) {
        int r = i >> 3, k = i & 7;
        s->inT[k][r] = phys[((size_t)(b0 + r) * T_) * P_ + k];
    }
    for (int i = tid; i < 540;  i += NTHR) s->sb[i]        = b_ih[i];
    for (int i = tid; i < 540;  i += NTHR) s->sb[540 + i]  = b_hh[i];
    for (int i = tid; i < 180;  i += NTHR) s->sb[1080 + i] = b_in[i];
    for (int i = tid; i < 180;  i += NTHR) s->sb[1260 + i] = b_o1[i];
    for (int i = tid; i < 64;   i += NTHR) s->sb[1440 + i] = b_o2[i];
    for (int i = tid; i < 180;  i += NTHR) s->sb[1504 + i] = b_hp[i];
    __syncthreads();

    // ---- h0 = latents @ W_hp^T + b_hp (uses catC = latents^T) ----
    if (tid < 360) {
        int j = tid >> 1, ro = (tid & 1) * 8;
        float acc[8] = {0,0,0,0,0,0,0,0};
        pcol<8, 16, 180, BT>(g_Wh4 + j, &s->catC[0][ro], acc);
        float bb = s->sb[1504 + j];
#pragma unroll
        for (int i = 0; i < 8; i++) s->hT[0][j][ro + i] = acc[i] + bb;
    }

    for (int t = 0; t < T_; t++) {
        const int cb = t & 1, nb = cb ^ 1;
        __syncthreads();   // (0) inT/catC/cur (from prev E) and hT[cb] ready

        // ---- B: xT = gelu(inT @ W_in^T + b_in)  (360 tasks, 2c x 4r) ----
        if (tid < 360) {
            const int p = tid >> 2, ro = (tid & 3) * 4;
            float acc0[4] = {0,0,0,0}, acc1[4] = {0,0,0,0};
            ppair4<36, 90>(g_Wb4p + p, &s->inT[0][0], ro, acc0, acc1);
            const int j0 = 2 * p;
            float bb0 = s->sb[1080 + j0], bb1 = s->sb[1080 + j0 + 1];
#pragma unroll
            for (int i = 0; i < 4; i++) {
                s->xT[j0][ro + i]     = gelu_f(acc0[i] + bb0);
                s->xT[j0 + 1][ro + i] = gelu_f(acc1[i] + bb1);
            }
        }
        __syncthreads();   // (1) xT ready

        // ---- C: gi/gh (540 tasks, 2c x 16r, PF ring) — unchanged from R13 ----
        if (tid < 540) {
            const int p = tid;
            const bool gh = (p >= 270);
            const float* act = gh ? &s->hT[cb][0][0] : &s->xT[0][0];
            const float4* wp = g_Wc4 + p;
            float acc0[16], acc1[16];
#pragma unroll
            for (int i = 0; i < 16; i++) { acc0[i] = 0.f; acc1[i] = 0.f; }
            float4 wc = wp[0];
            float4 wn = wp[540];
#pragma unroll 3
            for (int k2 = 0; k2 < 90; k2++) {
                float4 w = wc;
                wc = wn;
                int kpf = (k2 + 2 < 90) ? (k2 + 2) : 89;
                wn = wp[kpf * 540];
                const float* ap = act + (2 * k2) * BT;
                fma2x16(acc0, acc1, ap,      w.x, w.y);
                fma2x16(acc0, acc1, ap + BT, w.z, w.w);
            }
            const int j0 = 2 * p;
            float bb0 = s->sb[j0], bb1 = s->sb[j0 + 1];
            float* d0 = gh ? s->ghT[j0 - 540] : s->giT[j0];
            float* d1 = gh ? s->ghT[j0 - 539] : s->giT[j0 + 1];
#pragma unroll
            for (int rq = 0; rq < 4; rq++) {
                *(float4*)(d0 + rq * 4) =
                    make_float4(acc0[rq*4+0] + bb0, acc0[rq*4+1] + bb0,
                                acc0[rq*4+2] + bb0, acc0[rq*4+3] + bb0);
                *(float4*)(d1 + rq * 4) =
                    make_float4(acc1[rq*4+0] + bb1, acc1[rq*4+1] + bb1,
                                acc1[rq*4+2] + bb1, acc1[rq*4+3] + bb1);
            }
        }
        __syncthreads();   // (2) gi/gh ready

        // ---- gates: h_new -> hT[nb] only ----
        for (int i = tid; i < H_ * BT; i += NTHR) {
            int j = i >> 4, r = i & 15;
            float rg = sigmoid_f(s->giT[j][r]        + s->ghT[j][r]);
            float zg = sigmoid_f(s->giT[j + H_][r]   + s->ghT[j + H_][r]);
            float ng = tanhf    (s->giT[j + 2*H_][r] + rg * s->ghT[j + 2*H_][r]);
            s->hT[nb][j][r] = (1.f - zg) * ng + zg * s->hT[cb][j][r];
        }
        __syncthreads();   // (3) h_new ready

        // ---- D: oT = gelu([h_new ; cur] @ W_o1^T + b_o1)  (360 tasks, 2c x 4r) ----
        if (tid < 360) {
            const int p = tid >> 2, ro = (tid & 3) * 4;
            float acc0[4] = {0,0,0,0}, acc1[4] = {0,0,0,0};
            ppair4<90, 90>(g_Wd4a + p, &s->hT[nb][0][0], ro, acc0, acc1);  // K 0..179
            ppair4<32, 90>(g_Wd4b + p, &s->catC[0][0],   ro, acc0, acc1);  // K 180..243
            const int j0 = 2 * p;
            float bb0 = s->sb[1260 + j0], bb1 = s->sb[1260 + j0 + 1];
#pragma unroll
            for (int i = 0; i < 4; i++) {
                s->oT[j0][ro + i]     = gelu_f(acc0[i] + bb0);
                s->oT[j0 + 1][ro + i] = gelu_f(acc1[i] + bb1);
            }
        }
        __syncthreads();   // (4) oT ready; catC free to rewrite

        // ---- E: cur update + out store + next-step inT/catC; phys prefetch ----
        if (tid < 256) {
            int j = tid >> 2, ro = (tid & 3) * 4;
            float acc[4] = {0,0,0,0};
            pcol<4, 45, 64, BT>(g_We4 + j, &s->oT[0][ro], acc);
            float bb = s->sb[1440 + j];
#pragma unroll
            for (int i = 0; i < 4; i++) {
                int r = ro + i;
                float c = fminf(fmaxf(s->cur[r][j] + acc[i] + bb, 0.f), 1.f);
                s->cur[r][j]       = c;
                s->catC[j][r]      = c;
                s->inT[P_ + j][r]  = c;
                out[((size_t)(b0 + r) * T_ + t) * L_ + j] = c;
            }
        } else if (tid < 384 && t + 1 < T_) {
            const int u = tid - 256;          // 128 elems: phys(t+1)
            const int k = u >> 4, r = u & 15;
            s->inT[k][r] = phys[((size_t)(b0 + r) * T_ + (t + 1)) * P_ + k];
        }
    }
}

extern "C" void kernel_launch(void* const* d_in, const int* in_sizes, int n_in,
                              void* d_out, int out_size)
{
    const float* phys    = (const float*)d_in[0];
    const float* latents = (const float*)d_in[1];
    const float* W_in    = (const float*)d_in[2];
    const float* b_in    = (const float*)d_in[3];
    const float* W_hp    = (const float*)d_in[4];
    const float* b_hp    = (const float*)d_in[5];
    const float* W_ih    = (const float*)d_in[6];
    const float* b_ih    = (const float*)d_in[7];
    const float* W_hh    = (const float*)d_in[8];
    const float* b_hh    = (const float*)d_in[9];
    const float* W_o1    = (const float*)d_in[10];
    const float* b_o1    = (const float*)d_in[11];
    const float* W_o2    = (const float*)d_in[12];
    const float* b_o2    = (const float*)d_in[13];
    float* out = (float*)d_out;

    static bool attr_set = false;
    if (!attr_set) {
        cudaFuncSetAttribute(latent_rnn_kernel,
                             cudaFuncAttributeMaxDynamicSharedMemorySize,
                             (int)sizeof(Smem));
        attr_set = true;
    }

    prep_kernel<<<(N_C + N_B2 + N_DA + N_DB + N_E + N_H + 255) / 256, 256>>>(
        W_ih, W_hh, W_in, W_o1, W_o2, W_hp);

    latent_rnn_kernel<<<B_ / BT, NTHR, sizeof(Smem)>>>(
        phys, latents, b_in, b_hp, b_ih, b_hh, b_o1, b_o2, out);
}